// round 1
// baseline (speedup 1.0000x reference)
#include <cuda_runtime.h>
#include <cstdint>

#define N_NODES 50000
#define N_EDGES 800000
#define D 128
#define NCLS 64

// Scratch (allocations are forbidden; device globals are the sanctioned path)
__device__ __align__(16) float g_agg[N_NODES * D];
__device__ __align__(16) float g_h[N_NODES * D];

// ---------------------------------------------------------------------------
// Vectorized copy: initializes agg = x (the "+x" term of GIN with eps=0)
// ---------------------------------------------------------------------------
__global__ void copy_kernel(const float4* __restrict__ src, float4* __restrict__ dst, int n4) {
    int i = blockIdx.x * blockDim.x + threadIdx.x;
    if (i < n4) dst[i] = src[i];
}

// ---------------------------------------------------------------------------
// Scatter-add: one warp per edge. Each lane moves 16B (float4) of the 512B
// feature row: LDG.128 gather from x[src], RED.128 (red.global.add.v4.f32,
// no return trip) into agg[dst].
// ---------------------------------------------------------------------------
__global__ void __launch_bounds__(256) scatter_kernel(
    const float* __restrict__ x, float* __restrict__ agg,
    const int* __restrict__ src, const int* __restrict__ dst)
{
    int warp = (blockIdx.x * blockDim.x + threadIdx.x) >> 5;
    int lane = threadIdx.x & 31;
    if (warp >= N_EDGES) return;

    int s = __ldg(src + warp);   // broadcast within warp: single sector
    int d = __ldg(dst + warp);

    const float4* xrow = reinterpret_cast<const float4*>(x + (size_t)s * D);
    float4 v = xrow[lane];

    float* out = agg + (size_t)d * D + lane * 4;
    asm volatile("red.global.add.v4.f32 [%0], {%1,%2,%3,%4};"
                 :: "l"(out), "f"(v.x), "f"(v.y), "f"(v.z), "f"(v.w)
                 : "memory");
}

// ---------------------------------------------------------------------------
// Fused GEMM + bias + relu:  out[n, j] = relu( sum_k A[n,k] * W[j,k] + b[j] )
// A: [N_NODES, 128], W: [NOUT, 128], out: [N_NODES, NOUT]
// Block: 64 rows x NOUT cols. Full K=128 in smem; W stored transposed in smem
// for conflict-free float4 column reads. 256 threads, micro-tile RPT x 4.
// ---------------------------------------------------------------------------
template <int NOUT>
__global__ void __launch_bounds__(256) gemm_bias_relu_kernel(
    const float* __restrict__ A, const float* __restrict__ W,
    const float* __restrict__ b, float* __restrict__ out)
{
    constexpr int BM  = 64;
    constexpr int TX  = NOUT / 4;    // 32 (NOUT=128) or 16 (NOUT=64)
    constexpr int TY  = 256 / TX;    // 8 or 16
    constexpr int RPT = BM / TY;     // 8 or 4

    extern __shared__ float smem[];
    float* sX = smem;                // [BM][128]
    float* sW = smem + BM * D;       // [128][NOUT]  (W transposed)

    const int tid  = threadIdx.x;
    const int row0 = blockIdx.x * BM;

    // Load X tile (float4, coalesced). Guard tail rows with zeros.
    #pragma unroll
    for (int i = tid; i < BM * (D / 4); i += 256) {
        int r  = i >> 5;             // D/4 == 32
        int c4 = i & 31;
        int gr = row0 + r;
        float4 v = make_float4(0.f, 0.f, 0.f, 0.f);
        if (gr < N_NODES) v = reinterpret_cast<const float4*>(A + (size_t)gr * D)[c4];
        reinterpret_cast<float4*>(sX)[i] = v;
    }
    // Load W transposed: sW[k * NOUT + n] = W[n * 128 + k]  (W is tiny & L2-hot)
    #pragma unroll
    for (int i = tid; i < D * NOUT; i += 256) {
        int k = i / NOUT;
        int n = i - k * NOUT;
        sW[i] = __ldg(W + n * D + k);
    }
    __syncthreads();

    const int tx = tid % TX;
    const int ty = tid / TX;
    const int cbase = tx * 4;
    const int rbase = ty * RPT;

    float acc[RPT][4];
    #pragma unroll
    for (int r = 0; r < RPT; r++)
        #pragma unroll
        for (int c = 0; c < 4; c++) acc[r][c] = 0.f;

    #pragma unroll 4
    for (int k = 0; k < D; k++) {
        float4 bv = reinterpret_cast<const float4*>(sW + k * NOUT)[tx];  // conflict-free
        #pragma unroll
        for (int r = 0; r < RPT; r++) {
            float a = sX[(rbase + r) * D + k];  // warp-broadcast
            acc[r][0] += a * bv.x;
            acc[r][1] += a * bv.y;
            acc[r][2] += a * bv.z;
            acc[r][3] += a * bv.w;
        }
    }

    float4 bias = reinterpret_cast<const float4*>(b)[tx];
    #pragma unroll
    for (int r = 0; r < RPT; r++) {
        int row = row0 + rbase + r;
        if (row >= N_NODES) continue;
        float4 o;
        o.x = fmaxf(acc[r][0] + bias.x, 0.f);
        o.y = fmaxf(acc[r][1] + bias.y, 0.f);
        o.z = fmaxf(acc[r][2] + bias.z, 0.f);
        o.w = fmaxf(acc[r][3] + bias.w, 0.f);
        reinterpret_cast<float4*>(out + (size_t)row * NOUT + cbase)[0] = o;
    }
}

// ---------------------------------------------------------------------------
// Launch: 3 x (copy -> scatter -> gemm+bias+relu)
// ---------------------------------------------------------------------------
extern "C" void kernel_launch(void* const* d_in, const int* in_sizes, int n_in,
                              void* d_out, int out_size)
{
    const float* in_feat = (const float*)d_in[0];
    const float* W1 = (const float*)d_in[1];
    const float* b1 = (const float*)d_in[2];
    const float* W2 = (const float*)d_in[3];
    const float* b2 = (const float*)d_in[4];
    const float* W3 = (const float*)d_in[5];
    const float* b3 = (const float*)d_in[6];
    const int*   src = (const int*)d_in[7];
    const int*   dst = (const int*)d_in[8];
    float* out = (float*)d_out;

    float *agg, *h;
    cudaGetSymbolAddress((void**)&agg, g_agg);
    cudaGetSymbolAddress((void**)&h,   g_h);

    const int smem128 = (64 * D + D * 128) * (int)sizeof(float);  // 96 KB
    const int smem64  = (64 * D + D * 64)  * (int)sizeof(float);  // 64 KB
    cudaFuncSetAttribute(gemm_bias_relu_kernel<128>,
                         cudaFuncAttributeMaxDynamicSharedMemorySize, smem128);
    cudaFuncSetAttribute(gemm_bias_relu_kernel<64>,
                         cudaFuncAttributeMaxDynamicSharedMemorySize, smem64);

    const int n4 = N_NODES * D / 4;
    const int copy_blocks    = (n4 + 255) / 256;
    const int scatter_blocks = N_EDGES / 8;           // 8 warps/block, 1 warp/edge
    const int gemm_blocks    = (N_NODES + 63) / 64;

    // ---- Layer 1 ----
    copy_kernel<<<copy_blocks, 256>>>((const float4*)in_feat, (float4*)agg, n4);
    scatter_kernel<<<scatter_blocks, 256>>>(in_feat, agg, src, dst);
    gemm_bias_relu_kernel<128><<<gemm_blocks, 256, smem128>>>(agg, W1, b1, h);

    // ---- Layer 2 ----
    copy_kernel<<<copy_blocks, 256>>>((const float4*)h, (float4*)agg, n4);
    scatter_kernel<<<scatter_blocks, 256>>>(h, agg, src, dst);
    gemm_bias_relu_kernel<128><<<gemm_blocks, 256, smem128>>>(agg, W2, b2, h);

    // ---- Layer 3 ----
    copy_kernel<<<copy_blocks, 256>>>((const float4*)h, (float4*)agg, n4);
    scatter_kernel<<<scatter_blocks, 256>>>(h, agg, src, dst);
    gemm_bias_relu_kernel<64><<<gemm_blocks, 256, smem64>>>(agg, W3, b3, out);
}

// round 2
// speedup vs baseline: 1.3681x; 1.3681x over previous
#include <cuda_runtime.h>
#include <cstdint>

#define N_NODES 50000
#define N_EDGES 800000
#define D 128
#define NCLS 64

// ---------------------------------------------------------------------------
// Device-global scratch (allocations are forbidden)
// ---------------------------------------------------------------------------
__device__ __align__(16) float g_y[N_NODES * D];   // GEMM output per layer
__device__ __align__(16) float g_h[N_NODES * D];   // aggregated/activated output
__device__ int g_row_ptr[N_NODES + 1];
__device__ int g_cursor[N_NODES];
__device__ int g_cnt[N_NODES];
__device__ int g_col[N_EDGES];

// ---------------------------------------------------------------------------
// CSR construction: zero counts -> histogram -> scan -> fill
// ---------------------------------------------------------------------------
__global__ void zero_cnt_kernel(int* __restrict__ cnt) {
    int i = blockIdx.x * blockDim.x + threadIdx.x;
    if (i < N_NODES) cnt[i] = 0;
}

__global__ void hist_kernel(const int* __restrict__ dst, int* __restrict__ cnt) {
    int e = blockIdx.x * blockDim.x + threadIdx.x;
    if (e < N_EDGES) atomicAdd(cnt + dst[e], 1);   // no return use -> RED
}

// Single-block exclusive scan over N_NODES counts (runs once; a few us).
__global__ void __launch_bounds__(1024) scan_kernel(
    const int* __restrict__ cnt, int* __restrict__ row_ptr, int* __restrict__ cursor)
{
    __shared__ int buf[1024];
    __shared__ int carry;
    if (threadIdx.x == 0) carry = 0;
    __syncthreads();

    for (int base = 0; base < N_NODES; base += 1024) {
        int i = base + (int)threadIdx.x;
        int v = (i < N_NODES) ? cnt[i] : 0;
        buf[threadIdx.x] = v;
        __syncthreads();
        // Hillis-Steele inclusive scan
        #pragma unroll
        for (int off = 1; off < 1024; off <<= 1) {
            int t = (threadIdx.x >= (unsigned)off) ? buf[threadIdx.x - off] : 0;
            __syncthreads();
            buf[threadIdx.x] += t;
            __syncthreads();
        }
        int excl = carry + buf[threadIdx.x] - v;
        if (i < N_NODES) { row_ptr[i] = excl; cursor[i] = excl; }
        __syncthreads();
        if (threadIdx.x == 1023) carry += buf[1023];
        __syncthreads();
    }
    if (threadIdx.x == 0) row_ptr[N_NODES] = N_EDGES;
}

__global__ void fill_kernel(const int* __restrict__ src, const int* __restrict__ dst,
                            int* __restrict__ cursor, int* __restrict__ col)
{
    int e = blockIdx.x * blockDim.x + threadIdx.x;
    if (e < N_EDGES) {
        int pos = atomicAdd(cursor + dst[e], 1);
        col[pos] = src[e];
    }
}

// ---------------------------------------------------------------------------
// Pure GEMM:  y[n, j] = sum_k A[n,k] * W[j,k]
// 256 threads, BM=64 rows; each thread: 4 rows x 8 cols.
// Padded smem (stride +4 words) -> conflict-free, float4-aligned.
// ---------------------------------------------------------------------------
template <int NOUT>
__global__ void __launch_bounds__(256) gemm_kernel(
    const float* __restrict__ A, const float* __restrict__ W, float* __restrict__ y)
{
    constexpr int BM  = 64;
    constexpr int TX  = NOUT / 8;        // 16 (NOUT=128) or 8 (NOUT=64)
    constexpr int TY  = 256 / TX;        // 16 or 32
    constexpr int RPT = BM / TY;         // 4 or 2
    constexpr int SXS = D + 4;           // 132
    constexpr int SWS = NOUT + 4;

    extern __shared__ float smem[];
    float* sX = smem;                    // [BM][SXS]
    float* sW = smem + BM * SXS;         // [D][SWS]  (W transposed)

    const int tid  = threadIdx.x;
    const int row0 = blockIdx.x * BM;

    // X tile: coalesced float4 loads, padded float4 stores (SXS%4==0 -> aligned)
    #pragma unroll
    for (int i = tid; i < BM * (D / 4); i += 256) {
        int r  = i >> 5;                 // D/4 == 32
        int c4 = i & 31;
        int gr = row0 + r;
        float4 v = make_float4(0.f, 0.f, 0.f, 0.f);
        if (gr < N_NODES) v = reinterpret_cast<const float4*>(A + (size_t)gr * D)[c4];
        reinterpret_cast<float4*>(sX + r * SXS)[c4] = v;
    }
    // W tile: coalesced global read, transposed padded store
    #pragma unroll
    for (int i = tid; i < NOUT * D; i += 256) {
        int n = i >> 7;                  // D == 128
        int k = i & 127;
        sW[k * SWS + n] = W[i];
    }
    __syncthreads();

    const int tx = tid % TX;
    const int ty = tid / TX;
    const int cbase = tx * 8;
    const int rbase = ty * RPT;

    float acc[RPT][8];
    #pragma unroll
    for (int r = 0; r < RPT; r++)
        #pragma unroll
        for (int c = 0; c < 8; c++) acc[r][c] = 0.f;

    #pragma unroll 2
    for (int k = 0; k < D; k++) {
        float4 b0 = reinterpret_cast<const float4*>(sW + k * SWS + cbase)[0];
        float4 b1 = reinterpret_cast<const float4*>(sW + k * SWS + cbase)[1];
        float a[RPT];
        #pragma unroll
        for (int r = 0; r < RPT; r++) a[r] = sX[(rbase + r) * SXS + k];
        #pragma unroll
        for (int r = 0; r < RPT; r++) {
            acc[r][0] += a[r] * b0.x;  acc[r][1] += a[r] * b0.y;
            acc[r][2] += a[r] * b0.z;  acc[r][3] += a[r] * b0.w;
            acc[r][4] += a[r] * b1.x;  acc[r][5] += a[r] * b1.y;
            acc[r][6] += a[r] * b1.z;  acc[r][7] += a[r] * b1.w;
        }
    }

    #pragma unroll
    for (int r = 0; r < RPT; r++) {
        int row = row0 + rbase + r;
        if (row >= N_NODES) continue;
        float4 o0 = make_float4(acc[r][0], acc[r][1], acc[r][2], acc[r][3]);
        float4 o1 = make_float4(acc[r][4], acc[r][5], acc[r][6], acc[r][7]);
        float4* dst4 = reinterpret_cast<float4*>(y + (size_t)row * NOUT + cbase);
        dst4[0] = o0;
        dst4[1] = o1;
    }
}

// ---------------------------------------------------------------------------
// CSR aggregation + bias + relu:  out[n] = relu(y[n] + sum_{e: dst=n} y[src_e] + b)
// One warp per node, no atomics. DIMS=128: lane owns float4; DIMS=64: float2.
// ---------------------------------------------------------------------------
__global__ void __launch_bounds__(256) aggregate128_kernel(
    const float* __restrict__ y, const int* __restrict__ row_ptr,
    const int* __restrict__ col, const float* __restrict__ bias,
    float* __restrict__ out)
{
    int node = (blockIdx.x * blockDim.x + threadIdx.x) >> 5;
    int lane = threadIdx.x & 31;
    if (node >= N_NODES) return;

    int beg = __ldg(row_ptr + node);
    int end = __ldg(row_ptr + node + 1);

    const float4* base = reinterpret_cast<const float4*>(y);
    float4 acc = base[(size_t)node * 32 + lane];

    int j = beg;
    for (; j + 1 < end; j += 2) {
        int c0 = __ldg(col + j);
        int c1 = __ldg(col + j + 1);
        float4 v0 = base[(size_t)c0 * 32 + lane];
        float4 v1 = base[(size_t)c1 * 32 + lane];
        acc.x += v0.x; acc.y += v0.y; acc.z += v0.z; acc.w += v0.w;
        acc.x += v1.x; acc.y += v1.y; acc.z += v1.z; acc.w += v1.w;
    }
    if (j < end) {
        int c0 = __ldg(col + j);
        float4 v0 = base[(size_t)c0 * 32 + lane];
        acc.x += v0.x; acc.y += v0.y; acc.z += v0.z; acc.w += v0.w;
    }

    float4 b = reinterpret_cast<const float4*>(bias)[lane];
    float4 o;
    o.x = fmaxf(acc.x + b.x, 0.f);
    o.y = fmaxf(acc.y + b.y, 0.f);
    o.z = fmaxf(acc.z + b.z, 0.f);
    o.w = fmaxf(acc.w + b.w, 0.f);
    reinterpret_cast<float4*>(out)[(size_t)node * 32 + lane] = o;
}

__global__ void __launch_bounds__(256) aggregate64_kernel(
    const float* __restrict__ y, const int* __restrict__ row_ptr,
    const int* __restrict__ col, const float* __restrict__ bias,
    float* __restrict__ out)
{
    int node = (blockIdx.x * blockDim.x + threadIdx.x) >> 5;
    int lane = threadIdx.x & 31;
    if (node >= N_NODES) return;

    int beg = __ldg(row_ptr + node);
    int end = __ldg(row_ptr + node + 1);

    const float2* base = reinterpret_cast<const float2*>(y);
    float2 acc = base[(size_t)node * 32 + lane];

    int j = beg;
    for (; j + 1 < end; j += 2) {
        int c0 = __ldg(col + j);
        int c1 = __ldg(col + j + 1);
        float2 v0 = base[(size_t)c0 * 32 + lane];
        float2 v1 = base[(size_t)c1 * 32 + lane];
        acc.x += v0.x + v1.x;
        acc.y += v0.y + v1.y;
    }
    if (j < end) {
        int c0 = __ldg(col + j);
        float2 v0 = base[(size_t)c0 * 32 + lane];
        acc.x += v0.x; acc.y += v0.y;
    }

    float2 b = reinterpret_cast<const float2*>(bias)[lane];
    float2 o;
    o.x = fmaxf(acc.x + b.x, 0.f);
    o.y = fmaxf(acc.y + b.y, 0.f);
    reinterpret_cast<float2*>(out)[(size_t)node * 32 + lane] = o;
}

// ---------------------------------------------------------------------------
// Launch
// ---------------------------------------------------------------------------
extern "C" void kernel_launch(void* const* d_in, const int* in_sizes, int n_in,
                              void* d_out, int out_size)
{
    const float* in_feat = (const float*)d_in[0];
    const float* W1 = (const float*)d_in[1];
    const float* b1 = (const float*)d_in[2];
    const float* W2 = (const float*)d_in[3];
    const float* b2 = (const float*)d_in[4];
    const float* W3 = (const float*)d_in[5];
    const float* b3 = (const float*)d_in[6];
    const int*   src = (const int*)d_in[7];
    const int*   dst = (const int*)d_in[8];
    float* out = (float*)d_out;

    float *y, *h;
    int *row_ptr, *cursor, *cnt, *col;
    cudaGetSymbolAddress((void**)&y, g_y);
    cudaGetSymbolAddress((void**)&h, g_h);
    cudaGetSymbolAddress((void**)&row_ptr, g_row_ptr);
    cudaGetSymbolAddress((void**)&cursor, g_cursor);
    cudaGetSymbolAddress((void**)&cnt, g_cnt);
    cudaGetSymbolAddress((void**)&col, g_col);

    constexpr int SXS = D + 4;
    const int smem128 = (64 * SXS + D * (128 + 4)) * (int)sizeof(float);
    const int smem64  = (64 * SXS + D * (64 + 4))  * (int)sizeof(float);
    cudaFuncSetAttribute(gemm_kernel<128>,
                         cudaFuncAttributeMaxDynamicSharedMemorySize, smem128);
    cudaFuncSetAttribute(gemm_kernel<64>,
                         cudaFuncAttributeMaxDynamicSharedMemorySize, smem64);

    const int node_blocks  = (N_NODES + 255) / 256;
    const int edge_blocks  = (N_EDGES + 255) / 256;
    const int gemm_blocks  = (N_NODES + 63) / 64;
    const int agg_blocks   = (N_NODES * 32 + 255) / 256;  // one warp per node

    // ---- CSR build (once per launch) ----
    zero_cnt_kernel<<<node_blocks, 256>>>(cnt);
    hist_kernel<<<edge_blocks, 256>>>(dst, cnt);
    scan_kernel<<<1, 1024>>>(cnt, row_ptr, cursor);
    fill_kernel<<<edge_blocks, 256>>>(src, dst, cursor, col);

    // ---- Layer 1:  y = x@W1 ; h = relu(y + agg(y) + b1) ----
    gemm_kernel<128><<<gemm_blocks, 256, smem128>>>(in_feat, W1, y);
    aggregate128_kernel<<<agg_blocks, 256>>>(y, row_ptr, col, b1, h);

    // ---- Layer 2 ----
    gemm_kernel<128><<<gemm_blocks, 256, smem128>>>(h, W2, y);
    aggregate128_kernel<<<agg_blocks, 256>>>(y, row_ptr, col, b2, h);

    // ---- Layer 3 (64-dim aggregate directly into d_out) ----
    gemm_kernel<64><<<gemm_blocks, 256, smem64>>>(h, W3, y);
    aggregate64_kernel<<<agg_blocks, 256>>>(y, row_ptr, col, b3, out);
}

// round 3
// speedup vs baseline: 1.7487x; 1.2783x over previous
#include <cuda_runtime.h>
#include <cstdint>

#define N_NODES 50000
#define N_EDGES 800000
#define D 128
#define NCLS 64
#define SCAN_B 1024
#define SCAN_NBLK ((N_NODES + SCAN_B - 1) / SCAN_B)   // 49

// ---------------------------------------------------------------------------
// Device-global scratch
// ---------------------------------------------------------------------------
__device__ __align__(16) float g_y[N_NODES * D];
__device__ __align__(16) float g_h[N_NODES * D];
__device__ int g_row_ptr[N_NODES + 1];
__device__ int g_cursor[N_NODES];
__device__ int g_cnt[N_NODES];
__device__ int g_col[N_EDGES];
__device__ int g_partials[SCAN_NBLK];

// ---------------------------------------------------------------------------
// CSR: zero -> hist(x4 MLP) -> 3-phase scan -> fill(x4 MLP)
// ---------------------------------------------------------------------------
__global__ void zero_cnt_kernel(int* __restrict__ cnt) {
    int i = blockIdx.x * blockDim.x + threadIdx.x;
    if (i < N_NODES) cnt[i] = 0;
}

__global__ void __launch_bounds__(256) hist_kernel(
    const int* __restrict__ dst, int* __restrict__ cnt)
{
    int base = (blockIdx.x * blockDim.x + threadIdx.x) * 4;
    if (base + 3 < N_EDGES) {
        int4 d4 = *reinterpret_cast<const int4*>(dst + base);
        atomicAdd(cnt + d4.x, 1);
        atomicAdd(cnt + d4.y, 1);
        atomicAdd(cnt + d4.z, 1);
        atomicAdd(cnt + d4.w, 1);
    } else {
        for (int e = base; e < N_EDGES; e++) atomicAdd(cnt + dst[e], 1);
    }
}

// Phase 1: per-block exclusive scan (shuffle) + block totals
__global__ void __launch_bounds__(SCAN_B) scan_block_kernel(
    const int* __restrict__ cnt, int* __restrict__ row_ptr, int* __restrict__ partials)
{
    __shared__ int wsum[32];
    int i = blockIdx.x * SCAN_B + threadIdx.x;
    int lane = threadIdx.x & 31;
    int wid  = threadIdx.x >> 5;

    int v = (i < N_NODES) ? cnt[i] : 0;
    int x = v;
    #pragma unroll
    for (int off = 1; off < 32; off <<= 1) {
        int t = __shfl_up_sync(0xffffffffu, x, off);
        if (lane >= off) x += t;
    }
    if (lane == 31) wsum[wid] = x;
    __syncthreads();
    if (wid == 0) {
        int w = wsum[lane];
        #pragma unroll
        for (int off = 1; off < 32; off <<= 1) {
            int t = __shfl_up_sync(0xffffffffu, w, off);
            if (lane >= off) w += t;
        }
        wsum[lane] = w;
    }
    __syncthreads();

    int excl = x - v + (wid ? wsum[wid - 1] : 0);
    if (i < N_NODES) row_ptr[i] = excl;
    if (threadIdx.x == SCAN_B - 1) partials[blockIdx.x] = excl + v;
}

// Phase 2: single-warp exclusive scan of block totals (in place)
__global__ void scan_partials_kernel(int* __restrict__ partials) {
    int lane = threadIdx.x;
    int v = (lane < SCAN_NBLK) ? partials[lane] : 0;
    int x = v;
    // 64-wide scan via two warps in smem (SCAN_NBLK=49 <= 64)
    __shared__ int buf[64];
    buf[lane] = x;
    __syncthreads();
    #pragma unroll
    for (int off = 1; off < 64; off <<= 1) {
        int t = (lane >= off) ? buf[lane - off] : 0;
        __syncthreads();
        buf[lane] += t;
        __syncthreads();
    }
    if (lane < SCAN_NBLK) partials[lane] = buf[lane] - v;   // exclusive
}

// Phase 3: add block offsets, init cursor, close row_ptr
__global__ void __launch_bounds__(SCAN_B) scan_add_kernel(
    int* __restrict__ row_ptr, int* __restrict__ cursor, const int* __restrict__ partials)
{
    int i = blockIdx.x * SCAN_B + threadIdx.x;
    if (i < N_NODES) {
        int r = row_ptr[i] + partials[blockIdx.x];
        row_ptr[i] = r;
        cursor[i]  = r;
    }
    if (i == 0) row_ptr[N_NODES] = N_EDGES;
}

__global__ void __launch_bounds__(256) fill_kernel(
    const int* __restrict__ src, const int* __restrict__ dst,
    int* __restrict__ cursor, int* __restrict__ col)
{
    int base = (blockIdx.x * blockDim.x + threadIdx.x) * 4;
    if (base + 3 < N_EDGES) {
        int4 d4 = *reinterpret_cast<const int4*>(dst + base);
        int4 s4 = *reinterpret_cast<const int4*>(src + base);
        int p0 = atomicAdd(cursor + d4.x, 1);
        int p1 = atomicAdd(cursor + d4.y, 1);
        int p2 = atomicAdd(cursor + d4.z, 1);
        int p3 = atomicAdd(cursor + d4.w, 1);
        col[p0] = s4.x; col[p1] = s4.y; col[p2] = s4.z; col[p3] = s4.w;
    } else {
        for (int e = base; e < N_EDGES; e++) {
            int pos = atomicAdd(cursor + dst[e], 1);
            col[pos] = src[e];
        }
    }
}

// ---------------------------------------------------------------------------
// GEMM via packed fma.rn.f32x2 (2 fp32 FMAs per instruction, full precision)
// y[n,j] = sum_k A[n,k] * W[j,k].  BM=64 rows/block, 128 threads.
// NOUT=128: 16x8 threads, each 8 rows x 8 cols.  NOUT=64: 8x16, 4 rows x 8 cols.
// ---------------------------------------------------------------------------
template <int NOUT>
__global__ void __launch_bounds__(128) gemm_kernel(
    const float* __restrict__ A, const float* __restrict__ W, float* __restrict__ y)
{
    constexpr int BM  = 64;
    constexpr int TX  = NOUT / 8;        // 16 or 8
    constexpr int TY  = 128 / TX;        // 8 or 16
    constexpr int RPT = BM / TY;         // 8 or 4
    constexpr int SXS = D + 4;           // 132
    constexpr int SWS = NOUT + 4;        // 132 or 68 (both %4==0 -> 16B aligned)

    extern __shared__ float smem[];
    float* sX = smem;                    // [BM][SXS]
    float* sW = smem + BM * SXS;         // [D][SWS]  (W transposed, col pairs adjacent)

    const int tid  = threadIdx.x;
    const int row0 = blockIdx.x * BM;

    // X tile: coalesced float4 loads
    #pragma unroll
    for (int i = tid; i < BM * (D / 4); i += 128) {
        int r  = i >> 5;
        int c4 = i & 31;
        int gr = row0 + r;
        float4 v = make_float4(0.f, 0.f, 0.f, 0.f);
        if (gr < N_NODES) v = reinterpret_cast<const float4*>(A + (size_t)gr * D)[c4];
        reinterpret_cast<float4*>(sX + r * SXS)[c4] = v;
    }
    // W: coalesced float4 global reads, transposed scalar smem stores
    #pragma unroll
    for (int i = tid; i < NOUT * (D / 4); i += 128) {
        int n  = i >> 5;
        int k4 = i & 31;
        float4 v = reinterpret_cast<const float4*>(W)[i];
        sW[(k4 * 4 + 0) * SWS + n] = v.x;
        sW[(k4 * 4 + 1) * SWS + n] = v.y;
        sW[(k4 * 4 + 2) * SWS + n] = v.z;
        sW[(k4 * 4 + 3) * SWS + n] = v.w;
    }
    __syncthreads();

    const int tx = tid % TX;
    const int ty = tid / TX;
    const int cbase = tx * 8;
    const int rbase = ty * RPT;

    unsigned long long acc[RPT][4];
    #pragma unroll
    for (int r = 0; r < RPT; r++)
        #pragma unroll
        for (int c = 0; c < 4; c++) acc[r][c] = 0ULL;   // (0.f, 0.f)

    #pragma unroll 4
    for (int k = 0; k < D; k++) {
        // 8 columns = 4 f32x2 pairs, loaded as two 16B smem reads
        const ulonglong2* bp = reinterpret_cast<const ulonglong2*>(sW + k * SWS + cbase);
        ulonglong2 bA = bp[0];
        ulonglong2 bB = bp[1];
        #pragma unroll
        for (int r = 0; r < RPT; r++) {
            float a = sX[(rbase + r) * SXS + k];
            unsigned long long a2;
            asm("mov.b64 %0, {%1, %1};" : "=l"(a2) : "f"(a));
            asm("fma.rn.f32x2 %0, %1, %2, %0;" : "+l"(acc[r][0]) : "l"(a2), "l"(bA.x));
            asm("fma.rn.f32x2 %0, %1, %2, %0;" : "+l"(acc[r][1]) : "l"(a2), "l"(bA.y));
            asm("fma.rn.f32x2 %0, %1, %2, %0;" : "+l"(acc[r][2]) : "l"(a2), "l"(bB.x));
            asm("fma.rn.f32x2 %0, %1, %2, %0;" : "+l"(acc[r][3]) : "l"(a2), "l"(bB.y));
        }
    }

    #pragma unroll
    for (int r = 0; r < RPT; r++) {
        int row = row0 + rbase + r;
        if (row >= N_NODES) continue;
        float o[8];
        #pragma unroll
        for (int c = 0; c < 4; c++)
            asm("mov.b64 {%0, %1}, %2;" : "=f"(o[2*c]), "=f"(o[2*c+1]) : "l"(acc[r][c]));
        float4* dst4 = reinterpret_cast<float4*>(y + (size_t)row * NOUT + cbase);
        dst4[0] = make_float4(o[0], o[1], o[2], o[3]);
        dst4[1] = make_float4(o[4], o[5], o[6], o[7]);
    }
}

// ---------------------------------------------------------------------------
// CSR aggregation + bias + relu. One warp per node, 4 gathers in flight.
// ---------------------------------------------------------------------------
__global__ void __launch_bounds__(256) aggregate128_kernel(
    const float* __restrict__ y, const int* __restrict__ row_ptr,
    const int* __restrict__ col, const float* __restrict__ bias,
    float* __restrict__ out)
{
    int node = (blockIdx.x * blockDim.x + threadIdx.x) >> 5;
    int lane = threadIdx.x & 31;
    if (node >= N_NODES) return;

    int beg = __ldg(row_ptr + node);
    int end = __ldg(row_ptr + node + 1);

    const float4* base = reinterpret_cast<const float4*>(y);
    float4 acc = base[(size_t)node * 32 + lane];
    float4 acc2 = make_float4(0.f, 0.f, 0.f, 0.f);

    int j = beg;
    for (; j + 3 < end; j += 4) {
        int c0 = __ldg(col + j);
        int c1 = __ldg(col + j + 1);
        int c2 = __ldg(col + j + 2);
        int c3 = __ldg(col + j + 3);
        float4 v0 = base[(size_t)c0 * 32 + lane];
        float4 v1 = base[(size_t)c1 * 32 + lane];
        float4 v2 = base[(size_t)c2 * 32 + lane];
        float4 v3 = base[(size_t)c3 * 32 + lane];
        acc.x  += v0.x; acc.y  += v0.y; acc.z  += v0.z; acc.w  += v0.w;
        acc2.x += v1.x; acc2.y += v1.y; acc2.z += v1.z; acc2.w += v1.w;
        acc.x  += v2.x; acc.y  += v2.y; acc.z  += v2.z; acc.w  += v2.w;
        acc2.x += v3.x; acc2.y += v3.y; acc2.z += v3.z; acc2.w += v3.w;
    }
    for (; j < end; j++) {
        int c0 = __ldg(col + j);
        float4 v0 = base[(size_t)c0 * 32 + lane];
        acc.x += v0.x; acc.y += v0.y; acc.z += v0.z; acc.w += v0.w;
    }
    acc.x += acc2.x; acc.y += acc2.y; acc.z += acc2.z; acc.w += acc2.w;

    float4 b = reinterpret_cast<const float4*>(bias)[lane];
    float4 o;
    o.x = fmaxf(acc.x + b.x, 0.f);
    o.y = fmaxf(acc.y + b.y, 0.f);
    o.z = fmaxf(acc.z + b.z, 0.f);
    o.w = fmaxf(acc.w + b.w, 0.f);
    reinterpret_cast<float4*>(out)[(size_t)node * 32 + lane] = o;
}

__global__ void __launch_bounds__(256) aggregate64_kernel(
    const float* __restrict__ y, const int* __restrict__ row_ptr,
    const int* __restrict__ col, const float* __restrict__ bias,
    float* __restrict__ out)
{
    int node = (blockIdx.x * blockDim.x + threadIdx.x) >> 5;
    int lane = threadIdx.x & 31;
    if (node >= N_NODES) return;

    int beg = __ldg(row_ptr + node);
    int end = __ldg(row_ptr + node + 1);

    const float2* base = reinterpret_cast<const float2*>(y);
    float2 acc = base[(size_t)node * 32 + lane];
    float2 acc2 = make_float2(0.f, 0.f);

    int j = beg;
    for (; j + 3 < end; j += 4) {
        int c0 = __ldg(col + j);
        int c1 = __ldg(col + j + 1);
        int c2 = __ldg(col + j + 2);
        int c3 = __ldg(col + j + 3);
        float2 v0 = base[(size_t)c0 * 32 + lane];
        float2 v1 = base[(size_t)c1 * 32 + lane];
        float2 v2 = base[(size_t)c2 * 32 + lane];
        float2 v3 = base[(size_t)c3 * 32 + lane];
        acc.x  += v0.x; acc.y  += v0.y;
        acc2.x += v1.x; acc2.y += v1.y;
        acc.x  += v2.x; acc.y  += v2.y;
        acc2.x += v3.x; acc2.y += v3.y;
    }
    for (; j < end; j++) {
        int c0 = __ldg(col + j);
        float2 v0 = base[(size_t)c0 * 32 + lane];
        acc.x += v0.x; acc.y += v0.y;
    }
    acc.x += acc2.x; acc.y += acc2.y;

    float2 b = reinterpret_cast<const float2*>(bias)[lane];
    float2 o;
    o.x = fmaxf(acc.x + b.x, 0.f);
    o.y = fmaxf(acc.y + b.y, 0.f);
    reinterpret_cast<float2*>(out)[(size_t)node * 32 + lane] = o;
}

// ---------------------------------------------------------------------------
// Launch
// ---------------------------------------------------------------------------
extern "C" void kernel_launch(void* const* d_in, const int* in_sizes, int n_in,
                              void* d_out, int out_size)
{
    const float* in_feat = (const float*)d_in[0];
    const float* W1 = (const float*)d_in[1];
    const float* b1 = (const float*)d_in[2];
    const float* W2 = (const float*)d_in[3];
    const float* b2 = (const float*)d_in[4];
    const float* W3 = (const float*)d_in[5];
    const float* b3 = (const float*)d_in[6];
    const int*   src = (const int*)d_in[7];
    const int*   dst = (const int*)d_in[8];
    float* out = (float*)d_out;

    float *y, *h;
    int *row_ptr, *cursor, *cnt, *col, *partials;
    cudaGetSymbolAddress((void**)&y, g_y);
    cudaGetSymbolAddress((void**)&h, g_h);
    cudaGetSymbolAddress((void**)&row_ptr, g_row_ptr);
    cudaGetSymbolAddress((void**)&cursor, g_cursor);
    cudaGetSymbolAddress((void**)&cnt, g_cnt);
    cudaGetSymbolAddress((void**)&col, g_col);
    cudaGetSymbolAddress((void**)&partials, g_partials);

    const int smem128 = (64 * (D + 4) + D * (128 + 4)) * (int)sizeof(float);
    const int smem64  = (64 * (D + 4) + D * (64 + 4))  * (int)sizeof(float);
    cudaFuncSetAttribute(gemm_kernel<128>,
                         cudaFuncAttributeMaxDynamicSharedMemorySize, smem128);
    cudaFuncSetAttribute(gemm_kernel<64>,
                         cudaFuncAttributeMaxDynamicSharedMemorySize, smem64);

    const int node_blocks   = (N_NODES + 255) / 256;
    const int edge4_blocks  = (N_EDGES / 4 + 255) / 256;
    const int gemm_blocks   = (N_NODES + 63) / 64;
    const int agg_blocks    = (N_NODES * 32 + 255) / 256;

    // ---- CSR build ----
    zero_cnt_kernel<<<node_blocks, 256>>>(cnt);
    hist_kernel<<<edge4_blocks, 256>>>(dst, cnt);
    scan_block_kernel<<<SCAN_NBLK, SCAN_B>>>(cnt, row_ptr, partials);
    scan_partials_kernel<<<1, 64>>>(partials);
    scan_add_kernel<<<SCAN_NBLK, SCAN_B>>>(row_ptr, cursor, partials);
    fill_kernel<<<edge4_blocks, 256>>>(src, dst, cursor, col);

    // ---- Layer 1 ----
    gemm_kernel<128><<<gemm_blocks, 128, smem128>>>(in_feat, W1, y);
    aggregate128_kernel<<<agg_blocks, 256>>>(y, row_ptr, col, b1, h);

    // ---- Layer 2 ----
    gemm_kernel<128><<<gemm_blocks, 128, smem128>>>(h, W2, y);
    aggregate128_kernel<<<agg_blocks, 256>>>(y, row_ptr, col, b2, h);

    // ---- Layer 3 ----
    gemm_kernel<64><<<gemm_blocks, 128, smem64>>>(h, W3, y);
    aggregate64_kernel<<<agg_blocks, 256>>>(y, row_ptr, col, b3, out);
}